// round 16
// baseline (speedup 1.0000x reference)
#include <cuda_runtime.h>
#include <cuda_bf16.h>
#include <cstdint>

// Problem constants
#define BB 2
#define SS 2048
#define DD 1024
#define HH 16
#define HD 64
#define MTOT (BB*SS)           // 4096
#define A_ELEMS (MTOT*DD)      // 4,194,304
#define KV_ELEMS (BB*HH*SS*HD) // 4,194,304

// Scratch (device globals; no allocation allowed)
__device__ __nv_bfloat16 g_w1h[3072*1024];      // c_attn_w^T (N,K) hi
__device__ __nv_bfloat16 g_w1l[3072*1024];      // lo
__device__ __nv_bfloat16 g_w2h[1024*1024];      // c_proj_w^T (N,K) hi
__device__ __nv_bfloat16 g_w2l[1024*1024];
__device__ __nv_bfloat16 g_xh[A_ELEMS];         // x hi (M,K)
__device__ __nv_bfloat16 g_xl[A_ELEMS];
__device__ __nv_bfloat16 g_ah[A_ELEMS];         // attn out hi (M,K)
__device__ __nv_bfloat16 g_al[A_ELEMS];
__device__ __nv_bfloat16 g_qh[KV_ELEMS];        // q (B,H,S,hd) hi/lo
__device__ __nv_bfloat16 g_ql[KV_ELEMS];
__device__ __nv_bfloat16 g_kh[KV_ELEMS];        // k (B,H,S,hd) hi/lo
__device__ __nv_bfloat16 g_kl[KV_ELEMS];
__device__ __nv_bfloat16 g_vth[KV_ELEMS];       // v^T (B,H,hd,S) hi/lo
__device__ __nv_bfloat16 g_vtl[KV_ELEMS];

// ---------------------------------------------------------------------------
// Portable PTX helpers
// ---------------------------------------------------------------------------
__device__ __forceinline__ uint32_t smem_u32(const void* p) {
    uint32_t a;
    asm("{ .reg .u64 t; cvta.to.shared.u64 t, %1; cvt.u32.u64 %0, t; }"
        : "=r"(a) : "l"(p));
    return a;
}
__device__ __forceinline__ void cp_async16(uint32_t saddr, const void* gptr) {
    asm volatile("cp.async.ca.shared.global [%0], [%1], 16;"
                 :: "r"(saddr), "l"(gptr));
}
__device__ __forceinline__ void cp_commit() {
    asm volatile("cp.async.commit_group;");
}
template<int N>
__device__ __forceinline__ void cp_wait() {
    asm volatile("cp.async.wait_group %0;" :: "n"(N));
}
__device__ __forceinline__ void ldsm4(uint32_t r[4], uint32_t addr) {
    asm volatile("ldmatrix.sync.aligned.m8n8.x4.shared.b16 {%0,%1,%2,%3}, [%4];"
                 : "=r"(r[0]), "=r"(r[1]), "=r"(r[2]), "=r"(r[3]) : "r"(addr));
}
__device__ __forceinline__ void mma_bf16(float d[4], const uint32_t a[4],
                                         uint32_t b0, uint32_t b1) {
    asm volatile("mma.sync.aligned.m16n8k16.row.col.f32.bf16.bf16.f32 "
                 "{%0,%1,%2,%3}, {%4,%5,%6,%7}, {%8,%9}, {%0,%1,%2,%3};"
                 : "+f"(d[0]), "+f"(d[1]), "+f"(d[2]), "+f"(d[3])
                 : "r"(a[0]), "r"(a[1]), "r"(a[2]), "r"(a[3]),
                   "r"(b0), "r"(b1));
}

// ---------------------------------------------------------------------------
// Conversion kernels
// ---------------------------------------------------------------------------
__global__ __launch_bounds__(256) void conv_w(
    const float* __restrict__ W, __nv_bfloat16* __restrict__ hi,
    __nv_bfloat16* __restrict__ lo, int K, int N)
{
    __shared__ float t[32][33];
    const int nt = blockIdx.x * 32, kt = blockIdx.y * 32;
    const int tx = threadIdx.x & 31, ty = threadIdx.x >> 5;
    #pragma unroll
    for (int j = 0; j < 4; j++)
        t[ty + j*8][tx] = W[(size_t)(kt + ty + j*8) * N + nt + tx];
    __syncthreads();
    #pragma unroll
    for (int j = 0; j < 4; j++) {
        int n = nt + ty + j*8, k = kt + tx;
        float v = t[tx][ty + j*8];
        __nv_bfloat16 h = __float2bfloat16(v);
        float r = v - __bfloat162float(h);
        hi[(size_t)n * K + k] = h;
        lo[(size_t)n * K + k] = __float2bfloat16(r);
    }
}

__global__ __launch_bounds__(256) void conv_split(
    const float* __restrict__ X, __nv_bfloat16* __restrict__ hi,
    __nv_bfloat16* __restrict__ lo)
{
    int i = (blockIdx.x * 256 + threadIdx.x) * 4;
    float4 v = *(const float4*)(X + i);
    __nv_bfloat16 h0 = __float2bfloat16(v.x), h1 = __float2bfloat16(v.y);
    __nv_bfloat16 h2 = __float2bfloat16(v.z), h3 = __float2bfloat16(v.w);
    __nv_bfloat162 a; a.x = h0; a.y = h1;
    __nv_bfloat162 b; b.x = h2; b.y = h3;
    *(__nv_bfloat162*)(hi + i)     = a;
    *(__nv_bfloat162*)(hi + i + 2) = b;
    __nv_bfloat162 c, d;
    c.x = __float2bfloat16(v.x - __bfloat162float(h0));
    c.y = __float2bfloat16(v.y - __bfloat162float(h1));
    d.x = __float2bfloat16(v.z - __bfloat162float(h2));
    d.y = __float2bfloat16(v.w - __bfloat162float(h3));
    *(__nv_bfloat162*)(lo + i)     = c;
    *(__nv_bfloat162*)(lo + i + 2) = d;
}

// ---------------------------------------------------------------------------
// mma.sync GEMM, bf16x3 split. 128x128x32 tile, 16 warps (4x4), warp 32x32.
// 3-stage cp.async pipeline, one __syncthreads per stage. 512 threads.
// MODE 0: C = A@B^T + bias. MODE 1: qkv scatter (fp32 present + bf16 q/k/vT).
// ---------------------------------------------------------------------------
#define BK 32
#define AST 40
#define TILE_E (128*AST)
#define STAGE_E (4*TILE_E)
#define NSTG 3
#define GEMM_SMEM (NSTG*STAGE_E*2)

template<int MODE>
__global__ __launch_bounds__(512, 1) void gemm_mma(
    const __nv_bfloat16* __restrict__ Ahi, const __nv_bfloat16* __restrict__ Alo,
    const __nv_bfloat16* __restrict__ Bhi, const __nv_bfloat16* __restrict__ Blo,
    const float* __restrict__ bias, float* __restrict__ C,
    float* __restrict__ pk, float* __restrict__ pv,
    __nv_bfloat16* __restrict__ qhg, __nv_bfloat16* __restrict__ qlg,
    __nv_bfloat16* __restrict__ khg, __nv_bfloat16* __restrict__ klg,
    __nv_bfloat16* __restrict__ vthg, __nv_bfloat16* __restrict__ vtlg,
    int M, int N, int K)
{
    extern __shared__ __nv_bfloat16 smb[];
    const int tid = threadIdx.x;
    const int lane = tid & 31, wid = tid >> 5;
    const int warp_m = wid >> 2, warp_n = wid & 3;   // 4x4 warp grid
    const int bm = blockIdx.y * 128, bn = blockIdx.x * 128;
    const uint32_t sb = smem_u32(smb);

    const int nstage = K / BK;   // 32

    auto load_stage = [&](int st, int buf) {
        const int kc0 = st * BK;
        uint32_t sbase = sb + (uint32_t)buf * STAGE_E * 2;
        int row = tid >> 2, kc = (tid & 3) * 8;
        uint32_t so = (uint32_t)(row * AST + kc) * 2;
        size_t ga = (size_t)(bm + row) * K + kc0 + kc;
        size_t gb = (size_t)(bn + row) * K + kc0 + kc;
        cp_async16(sbase + 0*TILE_E*2 + so, Ahi + ga);
        cp_async16(sbase + 1*TILE_E*2 + so, Alo + ga);
        cp_async16(sbase + 2*TILE_E*2 + so, Bhi + gb);
        cp_async16(sbase + 3*TILE_E*2 + so, Blo + gb);
        cp_commit();
    };

    float d[2][4][4];
    #pragma unroll
    for (int mf = 0; mf < 2; mf++)
        #pragma unroll
        for (int nf = 0; nf < 4; nf++)
            #pragma unroll
            for (int r = 0; r < 4; r++) d[mf][nf][r] = 0.f;

    load_stage(0, 0);
    load_stage(1, 1);

    const int a_row = warp_m * 32 + (lane & 15);
    const int a_kh  = (lane >> 4) * 8;
    const int b_wn  = warp_n * 32;
    const int b_n   = (lane & 7) + ((lane >> 4) * 8);
    const int b_kh  = ((lane >> 3) & 1) * 8;

    for (int c = 0; c < nstage; c++) {
        if (c + 1 < nstage) cp_wait<1>(); else cp_wait<0>();
        __syncthreads();
        if (c + 2 < nstage) load_stage(c + 2, (c + 2) % NSTG);

        uint32_t tbase = sb + (uint32_t)((c % NSTG) * STAGE_E) * 2;
        #pragma unroll
        for (int ks = 0; ks < 2; ks++) {
            const int ko = ks * 16;
            uint32_t ah[2][4], al[2][4];
            #pragma unroll
            for (int mf = 0; mf < 2; mf++) {
                uint32_t off = (uint32_t)((a_row + mf * 16) * AST + ko + a_kh) * 2;
                ldsm4(ah[mf], tbase + 0*TILE_E*2 + off);
                ldsm4(al[mf], tbase + 1*TILE_E*2 + off);
            }
            #pragma unroll
            for (int g = 0; g < 2; g++) {          // 16-col B groups
                uint32_t bh[4], bl[4];
                uint32_t off = (uint32_t)((b_wn + g * 16 + b_n) * AST + ko + b_kh) * 2;
                ldsm4(bh, tbase + 2*TILE_E*2 + off);
                ldsm4(bl, tbase + 3*TILE_E*2 + off);
                #pragma unroll
                for (int mf = 0; mf < 2; mf++) {
                    #pragma unroll
                    for (int half = 0; half < 2; half++) {
                        int nf = g * 2 + half, p = half * 2;
                        mma_bf16(d[mf][nf], ah[mf], bh[p], bh[p+1]);
                        mma_bf16(d[mf][nf], ah[mf], bl[p], bl[p+1]);
                        mma_bf16(d[mf][nf], al[mf], bh[p], bh[p+1]);
                    }
                }
            }
        }
    }

    // Epilogue (warp covers 32 rows x 32 cols)
    const int er = lane >> 2;
    const int ec = (lane & 3) * 2;
    #pragma unroll
    for (int mf = 0; mf < 2; mf++) {
        #pragma unroll
        for (int half = 0; half < 2; half++) {
            int gm = bm + warp_m * 32 + mf * 16 + er + half * 8;
            #pragma unroll
            for (int nf = 0; nf < 4; nf++) {
                int gn = bn + warp_n * 32 + nf * 8 + ec;
                float v0 = d[mf][nf][half * 2 + 0] + bias[gn];
                float v1 = d[mf][nf][half * 2 + 1] + bias[gn + 1];
                if (MODE == 0) {
                    float2 vv = {v0, v1};
                    *(float2*)(C + (size_t)gm * N + gn) = vv;
                } else {
                    int part = gn >> 10;
                    int col  = gn & 1023;
                    int h = col >> 6, dd = col & 63;   // dd even
                    int b = gm >> 11, s = gm & 2047;
                    size_t idx = (((size_t)(b * HH + h)) * SS + s) * HD + dd;
                    __nv_bfloat162 hh, ll;
                    hh.x = __float2bfloat16(v0);
                    hh.y = __float2bfloat16(v1);
                    ll.x = __float2bfloat16(v0 - __bfloat162float(hh.x));
                    ll.y = __float2bfloat16(v1 - __bfloat162float(hh.y));
                    if (part == 0) {
                        *(__nv_bfloat162*)(qhg + idx) = hh;
                        *(__nv_bfloat162*)(qlg + idx) = ll;
                    } else if (part == 1) {
                        float2 vv = {v0, v1};
                        *(float2*)(pk + idx) = vv;
                        *(__nv_bfloat162*)(khg + idx) = hh;
                        *(__nv_bfloat162*)(klg + idx) = ll;
                    } else {
                        float2 vv = {v0, v1};
                        *(float2*)(pv + idx) = vv;
                        size_t it = (((size_t)(b * HH + h)) * HD + dd) * SS + s;
                        vthg[it]      = hh.x;
                        vthg[it + SS] = hh.y;
                        vtlg[it]      = ll.x;
                        vtlg[it + SS] = ll.y;
                    }
                }
            }
        }
    }
}

// ---------------------------------------------------------------------------
// HMMA flash attention. BM=256 (16 warps x 16 rows), BN=64 keys/stage,
// 3-stage cp.async pipeline, one __syncthreads per tile. 512 threads.
// ---------------------------------------------------------------------------
#define ATLD 72                       // smem row stride (elems)
#define AT_OQH 0
#define AT_OQL (256*ATLD)             // 18432
#define AT_OST (2*256*ATLD)           // 36864
#define AT_KVT (64*ATLD)              // 4608 elems per sub-tile
#define AT_STAGE (4*AT_KVT)           // 18432 elems
#define AT_NSTG 3
#define AT_SMEM_B ((AT_OST + AT_NSTG*AT_STAGE)*2)   // 184320 bytes

__global__ __launch_bounds__(512, 1) void attn_mma(
    const __nv_bfloat16* __restrict__ qh, const __nv_bfloat16* __restrict__ ql,
    const __nv_bfloat16* __restrict__ kh, const __nv_bfloat16* __restrict__ kl,
    const __nv_bfloat16* __restrict__ vth, const __nv_bfloat16* __restrict__ vtl,
    __nv_bfloat16* __restrict__ Oh, __nv_bfloat16* __restrict__ Ol)
{
    extern __shared__ __nv_bfloat16 smb[];
    const uint32_t sb = smem_u32(smb);
    const int tid = threadIdx.x, lane = tid & 31, wid = tid >> 5;
    const int qt = 7 - blockIdx.x, bh = blockIdx.y;
    const int q0 = qt * 256;
    const int b = bh >> 4, h = bh & 15;

    // Q tiles (hi/lo), 256x64 (joins commit group 0)
    {
        const __nv_bfloat16* qhb = qh + ((size_t)bh * SS + q0) * HD;
        const __nv_bfloat16* qlb = ql + ((size_t)bh * SS + q0) * HD;
        #pragma unroll
        for (int i = 0; i < 4; i++) {
            int e = tid + i * 512;
            int row = e >> 3, c16 = e & 7;
            uint32_t so = (uint32_t)(row * ATLD + c16 * 8) * 2;
            cp_async16(sb + AT_OQH*2 + so, qhb + row * HD + c16 * 8);
            cp_async16(sb + AT_OQL*2 + so, qlb + row * HD + c16 * 8);
        }
    }

    const int ntile = 4 * (qt + 1);
    auto load_kv = [&](int kt, int buf) {
        const int k0 = kt * 64;
        uint32_t base = sb + (uint32_t)(AT_OST + buf * AT_STAGE) * 2;
        int row = tid >> 3, c16 = tid & 7;
        uint32_t so = (uint32_t)(row * ATLD + c16 * 8) * 2;
        size_t gk = ((size_t)bh * SS + k0 + row) * HD + c16 * 8;
        size_t gv = ((size_t)bh * HD + row) * SS + k0 + c16 * 8;
        cp_async16(base + 0*AT_KVT*2 + so, kh + gk);
        cp_async16(base + 1*AT_KVT*2 + so, kl + gk);
        cp_async16(base + 2*AT_KVT*2 + so, vth + gv);
        cp_async16(base + 3*AT_KVT*2 + so, vtl + gv);
        cp_commit();
    };
    load_kv(0, 0);   // group 0 also covers the Q chunks
    load_kv(1, 1);

    const int er = lane >> 2, ec = (lane & 3) * 2;
    const int a_row = wid * 16 + (lane & 15);
    const int a_kh = (lane >> 4) * 8;
    const int b_n = (lane & 7) + ((lane >> 4) * 8);
    const int b_kh = ((lane >> 3) & 1) * 8;

    float m0 = -1e30f, m1 = -1e30f, l0 = 0.f, l1 = 0.f;
    float o[8][4];
    #pragma unroll
    for (int nf = 0; nf < 8; nf++)
        #pragma unroll
        for (int r = 0; r < 4; r++) o[nf][r] = 0.f;

    for (int kt = 0; kt < ntile; kt++) {
        if (kt + 1 < ntile) cp_wait<1>(); else cp_wait<0>();
        __syncthreads();
        if (kt + 2 < ntile) load_kv(kt + 2, (kt + 2) % AT_NSTG);

        const uint32_t stg = sb + (uint32_t)(AT_OST + (kt % AT_NSTG) * AT_STAGE) * 2;
        const int k0 = kt * 64;

        // S = Q K^T (x3 split)
        float c[8][4];
        #pragma unroll
        for (int nf = 0; nf < 8; nf++)
            #pragma unroll
            for (int r = 0; r < 4; r++) c[nf][r] = 0.f;

        #pragma unroll
        for (int ks = 0; ks < 4; ks++) {
            uint32_t aoff = (uint32_t)(a_row * ATLD + ks * 16 + a_kh) * 2;
            uint32_t aH[4], aL[4];
            ldsm4(aH, sb + AT_OQH*2 + aoff);
            ldsm4(aL, sb + AT_OQL*2 + aoff);
            #pragma unroll
            for (int q = 0; q < 4; q++) {
                uint32_t bH[4], bL[4];
                uint32_t boff = (uint32_t)((q * 16 + b_n) * ATLD + ks * 16 + b_kh) * 2;
                ldsm4(bH, stg + 0*AT_KVT*2 + boff);
                ldsm4(bL, stg + 1*AT_KVT*2 + boff);
                #pragma unroll
                for (int half = 0; half < 2; half++) {
                    int nf = q * 2 + half, p = half * 2;
                    mma_bf16(c[nf], aH, bH[p], bH[p+1]);
                    mma_bf16(c[nf], aH, bL[p], bL[p+1]);
                    mma_bf16(c[nf], aL, bH[p], bH[p+1]);
                }
            }
        }

        // scale + causal mask
        const int qi0 = q0 + wid * 16 + er;
        if (k0 + 63 > q0 + wid * 16) {
            #pragma unroll
            for (int nf = 0; nf < 8; nf++) {
                int jg = k0 + nf * 8 + ec;
                c[nf][0] = (jg     <= qi0    ) ? c[nf][0] * 0.125f : -1e10f;
                c[nf][1] = (jg + 1 <= qi0    ) ? c[nf][1] * 0.125f : -1e10f;
                c[nf][2] = (jg     <= qi0 + 8) ? c[nf][2] * 0.125f : -1e10f;
                c[nf][3] = (jg + 1 <= qi0 + 8) ? c[nf][3] * 0.125f : -1e10f;
            }
        } else {
            #pragma unroll
            for (int nf = 0; nf < 8; nf++)
                #pragma unroll
                for (int r = 0; r < 4; r++) c[nf][r] *= 0.125f;
        }

        // online softmax (rows er, er+8; quad-lane reduction)
        float rm0 = -1e30f, rm1 = -1e30f;
        #pragma unroll
        for (int nf = 0; nf < 8; nf++) {
            rm0 = fmaxf(rm0, fmaxf(c[nf][0], c[nf][1]));
            rm1 = fmaxf(rm1, fmaxf(c[nf][2], c[nf][3]));
        }
        #pragma unroll
        for (int off = 1; off < 4; off <<= 1) {
            rm0 = fmaxf(rm0, __shfl_xor_sync(0xffffffffu, rm0, off));
            rm1 = fmaxf(rm1, __shfl_xor_sync(0xffffffffu, rm1, off));
        }
        float mn0 = fmaxf(m0, rm0), mn1 = fmaxf(m1, rm1);
        float sc0 = __expf(m0 - mn0), sc1 = __expf(m1 - mn1);
        float rs0 = 0.f, rs1 = 0.f;
        #pragma unroll
        for (int nf = 0; nf < 8; nf++) {
            c[nf][0] = __expf(c[nf][0] - mn0);
            c[nf][1] = __expf(c[nf][1] - mn0);
            c[nf][2] = __expf(c[nf][2] - mn1);
            c[nf][3] = __expf(c[nf][3] - mn1);
            rs0 += c[nf][0] + c[nf][1];
            rs1 += c[nf][2] + c[nf][3];
        }
        #pragma unroll
        for (int off = 1; off < 4; off <<= 1) {
            rs0 += __shfl_xor_sync(0xffffffffu, rs0, off);
            rs1 += __shfl_xor_sync(0xffffffffu, rs1, off);
        }
        l0 = l0 * sc0 + rs0;  l1 = l1 * sc1 + rs1;
        m0 = mn0;  m1 = mn1;
        #pragma unroll
        for (int nf = 0; nf < 8; nf++) {
            o[nf][0] *= sc0; o[nf][1] *= sc0;
            o[nf][2] *= sc1; o[nf][3] *= sc1;
        }

        // O += P V  (x3 split; P frags re-packed from accumulators)
        #pragma unroll
        for (int ks = 0; ks < 4; ks++) {
            uint32_t pH[4], pL[4];
            {
                float p00 = c[2*ks][0],   p01 = c[2*ks][1];
                float p10 = c[2*ks][2],   p11 = c[2*ks][3];
                float p20 = c[2*ks+1][0], p21 = c[2*ks+1][1];
                float p30 = c[2*ks+1][2], p31 = c[2*ks+1][3];
                __nv_bfloat162 h0 = __floats2bfloat162_rn(p00, p01);
                __nv_bfloat162 h1 = __floats2bfloat162_rn(p10, p11);
                __nv_bfloat162 h2 = __floats2bfloat162_rn(p20, p21);
                __nv_bfloat162 h3 = __floats2bfloat162_rn(p30, p31);
                pH[0] = *(uint32_t*)&h0; pH[1] = *(uint32_t*)&h1;
                pH[2] = *(uint32_t*)&h2; pH[3] = *(uint32_t*)&h3;
                __nv_bfloat162 l0v = __floats2bfloat162_rn(p00 - __bfloat162float(h0.x), p01 - __bfloat162float(h0.y));
                __nv_bfloat162 l1v = __floats2bfloat162_rn(p10 - __bfloat162float(h1.x), p11 - __bfloat162float(h1.y));
                __nv_bfloat162 l2v = __floats2bfloat162_rn(p20 - __bfloat162float(h2.x), p21 - __bfloat162float(h2.y));
                __nv_bfloat162 l3v = __floats2bfloat162_rn(p30 - __bfloat162float(h3.x), p31 - __bfloat162float(h3.y));
                pL[0] = *(uint32_t*)&l0v; pL[1] = *(uint32_t*)&l1v;
                pL[2] = *(uint32_t*)&l2v; pL[3] = *(uint32_t*)&l3v;
            }
            #pragma unroll
            for (int qd = 0; qd < 4; qd++) {
                uint32_t vH[4], vL[4];
                uint32_t boff = (uint32_t)((qd * 16 + b_n) * ATLD + ks * 16 + b_kh) * 2;
                ldsm4(vH, stg + 2*AT_KVT*2 + boff);
                ldsm4(vL, stg + 3*AT_KVT*2 + boff);
                #pragma unroll
                for (int half = 0; half < 2; half++) {
                    int nf = qd * 2 + half, p = half * 2;
                    mma_bf16(o[nf], pH, vH[p], vH[p+1]);
                    mma_bf16(o[nf], pH, vL[p], vL[p+1]);
                    mma_bf16(o[nf], pL, vH[p], vH[p+1]);
                }
            }
        }
    }

    // epilogue: write bf16 hi/lo merged (B,S,D)
    const float i0 = 1.f / l0, i1 = 1.f / l1;
    #pragma unroll
    for (int nf = 0; nf < 8; nf++) {
        int col = nf * 8 + ec;
        int row0 = q0 + wid * 16 + er;
        size_t off0 = ((size_t)(b * SS + row0)) * DD + h * HD + col;
        size_t off1 = off0 + (size_t)8 * DD;
        float a0 = o[nf][0] * i0, a1 = o[nf][1] * i0;
        float a2 = o[nf][2] * i1, a3 = o[nf][3] * i1;
        __nv_bfloat162 hh0, hh1, ll0, ll1;
        hh0.x = __float2bfloat16(a0); hh0.y = __float2bfloat16(a1);
        hh1.x = __float2bfloat16(a2); hh1.y = __float2bfloat16(a3);
        ll0.x = __float2bfloat16(a0 - __bfloat162float(hh0.x));
        ll0.y = __float2bfloat16(a1 - __bfloat162float(hh0.y));
        ll1.x = __float2bfloat16(a2 - __bfloat162float(hh1.x));
        ll1.y = __float2bfloat16(a3 - __bfloat162float(hh1.y));
        *(__nv_bfloat162*)(Oh + off0) = hh0;
        *(__nv_bfloat162*)(Ol + off0) = ll0;
        *(__nv_bfloat162*)(Oh + off1) = hh1;
        *(__nv_bfloat162*)(Ol + off1) = ll1;
    }
}

// ---------------------------------------------------------------------------
extern "C" void kernel_launch(void* const* d_in, const int* in_sizes, int n_in,
                              void* d_out, int out_size)
{
    const float* x        = (const float*)d_in[0];
    const float* c_attn_w = (const float*)d_in[1];
    const float* c_attn_b = (const float*)d_in[2];
    const float* c_proj_w = (const float*)d_in[3];
    const float* c_proj_b = (const float*)d_in[4];

    float* out   = (float*)d_out;
    float* a_out = out;
    float* pk    = out + A_ELEMS;
    float* pv    = pk + KV_ELEMS;

    __nv_bfloat16 *w1h, *w1l, *w2h, *w2l, *xh, *xl, *ah, *al;
    __nv_bfloat16 *qh, *ql, *kh, *kl, *vth, *vtl;
    cudaGetSymbolAddress((void**)&w1h, g_w1h);
    cudaGetSymbolAddress((void**)&w1l, g_w1l);
    cudaGetSymbolAddress((void**)&w2h, g_w2h);
    cudaGetSymbolAddress((void**)&w2l, g_w2l);
    cudaGetSymbolAddress((void**)&xh, g_xh);
    cudaGetSymbolAddress((void**)&xl, g_xl);
    cudaGetSymbolAddress((void**)&ah, g_ah);
    cudaGetSymbolAddress((void**)&al, g_al);
    cudaGetSymbolAddress((void**)&qh, g_qh);
    cudaGetSymbolAddress((void**)&ql, g_ql);
    cudaGetSymbolAddress((void**)&kh, g_kh);
    cudaGetSymbolAddress((void**)&kl, g_kl);
    cudaGetSymbolAddress((void**)&vth, g_vth);
    cudaGetSymbolAddress((void**)&vtl, g_vtl);

    cudaFuncSetAttribute(gemm_mma<0>, cudaFuncAttributeMaxDynamicSharedMemorySize, GEMM_SMEM);
    cudaFuncSetAttribute(gemm_mma<1>, cudaFuncAttributeMaxDynamicSharedMemorySize, GEMM_SMEM);
    cudaFuncSetAttribute(attn_mma, cudaFuncAttributeMaxDynamicSharedMemorySize, AT_SMEM_B);

    // 0) conversions
    conv_w<<<dim3(3072/32, 1024/32), 256>>>(c_attn_w, w1h, w1l, DD, 3*DD);
    conv_w<<<dim3(1024/32, 1024/32), 256>>>(c_proj_w, w2h, w2l, DD, DD);
    conv_split<<<A_ELEMS/1024, 256>>>(x, xh, xl);

    // 1) qkv = x @ c_attn_w + b -> present fp32 + q/k/vT bf16 hi/lo
    gemm_mma<1><<<dim3(3*DD/128, MTOT/128), 512, GEMM_SMEM>>>(
        xh, xl, w1h, w1l, c_attn_b, nullptr, pk, pv,
        qh, ql, kh, kl, vth, vtl, MTOT, 3*DD, DD);

    // 2) attention (HMMA, BM=256) -> bf16 hi/lo
    attn_mma<<<dim3(SS/256, BB*HH), 512, AT_SMEM_B>>>(
        qh, ql, kh, kl, vth, vtl, ah, al);

    // 3) proj (HMMA)
    gemm_mma<0><<<dim3(DD/128, MTOT/128), 512, GEMM_SMEM>>>(
        ah, al, w2h, w2l, c_proj_b, a_out, nullptr, nullptr,
        nullptr, nullptr, nullptr, nullptr, nullptr, nullptr, MTOT, DD, DD);
}

// round 17
// speedup vs baseline: 1.1741x; 1.1741x over previous
#include <cuda_runtime.h>
#include <cuda_bf16.h>
#include <cstdint>

// Problem constants
#define BB 2
#define SS 2048
#define DD 1024
#define HH 16
#define HD 64
#define MTOT (BB*SS)           // 4096
#define A_ELEMS (MTOT*DD)      // 4,194,304
#define KV_ELEMS (BB*HH*SS*HD) // 4,194,304

// Scratch (device globals; no allocation allowed)
__device__ __nv_bfloat16 g_w1h[3072*1024];      // c_attn_w^T (N,K) hi
__device__ __nv_bfloat16 g_w1l[3072*1024];      // lo
__device__ __nv_bfloat16 g_w2h[1024*1024];      // c_proj_w^T (N,K) hi
__device__ __nv_bfloat16 g_w2l[1024*1024];
__device__ __nv_bfloat16 g_xh[A_ELEMS];         // x hi (M,K)
__device__ __nv_bfloat16 g_xl[A_ELEMS];
__device__ __nv_bfloat16 g_ah[A_ELEMS];         // attn out hi (M,K)
__device__ __nv_bfloat16 g_al[A_ELEMS];
__device__ __nv_bfloat16 g_qh[KV_ELEMS];        // q (B,H,S,hd) hi/lo
__device__ __nv_bfloat16 g_ql[KV_ELEMS];
__device__ __nv_bfloat16 g_kh[KV_ELEMS];        // k (B,H,S,hd) hi/lo
__device__ __nv_bfloat16 g_kl[KV_ELEMS];
__device__ __nv_bfloat16 g_vth[KV_ELEMS];       // v^T (B,H,hd,S) hi/lo
__device__ __nv_bfloat16 g_vtl[KV_ELEMS];

// ---------------------------------------------------------------------------
// Portable PTX helpers
// ---------------------------------------------------------------------------
__device__ __forceinline__ uint32_t smem_u32(const void* p) {
    uint32_t a;
    asm("{ .reg .u64 t; cvta.to.shared.u64 t, %1; cvt.u32.u64 %0, t; }"
        : "=r"(a) : "l"(p));
    return a;
}
__device__ __forceinline__ void cp_async16(uint32_t saddr, const void* gptr) {
    asm volatile("cp.async.ca.shared.global [%0], [%1], 16;"
                 :: "r"(saddr), "l"(gptr));
}
__device__ __forceinline__ void cp_commit() {
    asm volatile("cp.async.commit_group;");
}
template<int N>
__device__ __forceinline__ void cp_wait() {
    asm volatile("cp.async.wait_group %0;" :: "n"(N));
}
__device__ __forceinline__ void ldsm4(uint32_t r[4], uint32_t addr) {
    asm volatile("ldmatrix.sync.aligned.m8n8.x4.shared.b16 {%0,%1,%2,%3}, [%4];"
                 : "=r"(r[0]), "=r"(r[1]), "=r"(r[2]), "=r"(r[3]) : "r"(addr));
}
__device__ __forceinline__ void mma_bf16(float d[4], const uint32_t a[4],
                                         uint32_t b0, uint32_t b1) {
    asm volatile("mma.sync.aligned.m16n8k16.row.col.f32.bf16.bf16.f32 "
                 "{%0,%1,%2,%3}, {%4,%5,%6,%7}, {%8,%9}, {%0,%1,%2,%3};"
                 : "+f"(d[0]), "+f"(d[1]), "+f"(d[2]), "+f"(d[3])
                 : "r"(a[0]), "r"(a[1]), "r"(a[2]), "r"(a[3]),
                   "r"(b0), "r"(b1));
}

// ---------------------------------------------------------------------------
// Conversion kernels
// ---------------------------------------------------------------------------
__global__ __launch_bounds__(256) void conv_w(
    const float* __restrict__ W, __nv_bfloat16* __restrict__ hi,
    __nv_bfloat16* __restrict__ lo, int K, int N)
{
    __shared__ float t[32][33];
    const int nt = blockIdx.x * 32, kt = blockIdx.y * 32;
    const int tx = threadIdx.x & 31, ty = threadIdx.x >> 5;
    #pragma unroll
    for (int j = 0; j < 4; j++)
        t[ty + j*8][tx] = W[(size_t)(kt + ty + j*8) * N + nt + tx];
    __syncthreads();
    #pragma unroll
    for (int j = 0; j < 4; j++) {
        int n = nt + ty + j*8, k = kt + tx;
        float v = t[tx][ty + j*8];
        __nv_bfloat16 h = __float2bfloat16(v);
        float r = v - __bfloat162float(h);
        hi[(size_t)n * K + k] = h;
        lo[(size_t)n * K + k] = __float2bfloat16(r);
    }
}

__global__ __launch_bounds__(256) void conv_split(
    const float* __restrict__ X, __nv_bfloat16* __restrict__ hi,
    __nv_bfloat16* __restrict__ lo)
{
    int i = (blockIdx.x * 256 + threadIdx.x) * 4;
    float4 v = *(const float4*)(X + i);
    __nv_bfloat16 h0 = __float2bfloat16(v.x), h1 = __float2bfloat16(v.y);
    __nv_bfloat16 h2 = __float2bfloat16(v.z), h3 = __float2bfloat16(v.w);
    __nv_bfloat162 a; a.x = h0; a.y = h1;
    __nv_bfloat162 b; b.x = h2; b.y = h3;
    *(__nv_bfloat162*)(hi + i)     = a;
    *(__nv_bfloat162*)(hi + i + 2) = b;
    __nv_bfloat162 c, d;
    c.x = __float2bfloat16(v.x - __bfloat162float(h0));
    c.y = __float2bfloat16(v.y - __bfloat162float(h1));
    d.x = __float2bfloat16(v.z - __bfloat162float(h2));
    d.y = __float2bfloat16(v.w - __bfloat162float(h3));
    *(__nv_bfloat162*)(lo + i)     = c;
    *(__nv_bfloat162*)(lo + i + 2) = d;
}

// ---------------------------------------------------------------------------
// mma.sync GEMM, bf16x3 split. CTA 256x128x32, 8 warps (4x2), warp 64x64.
// Split terms issued in 3 separate passes (no accumulator RAW back-to-back).
// 3-stage cp.async pipeline. 256 threads.
// MODE 0: C = A@B^T + bias. MODE 1: qkv scatter (fp32 present + bf16 q/k/vT).
// ---------------------------------------------------------------------------
#define BK 32
#define AST 40
#define ATILE_E (256*AST)                 // 10240 elems
#define BTILE_E (128*AST)                 // 5120 elems
#define STAGE_E (2*ATILE_E + 2*BTILE_E)   // 30720 elems
#define NSTG 3
#define GEMM_SMEM (NSTG*STAGE_E*2)        // 184320 bytes
#define OFF_AHI 0
#define OFF_ALO (ATILE_E)
#define OFF_BHI (2*ATILE_E)
#define OFF_BLO (2*ATILE_E + BTILE_E)

template<int MODE>
__global__ __launch_bounds__(256, 1) void gemm_mma(
    const __nv_bfloat16* __restrict__ Ahi, const __nv_bfloat16* __restrict__ Alo,
    const __nv_bfloat16* __restrict__ Bhi, const __nv_bfloat16* __restrict__ Blo,
    const float* __restrict__ bias, float* __restrict__ C,
    float* __restrict__ pk, float* __restrict__ pv,
    __nv_bfloat16* __restrict__ qhg, __nv_bfloat16* __restrict__ qlg,
    __nv_bfloat16* __restrict__ khg, __nv_bfloat16* __restrict__ klg,
    __nv_bfloat16* __restrict__ vthg, __nv_bfloat16* __restrict__ vtlg,
    int M, int N, int K)
{
    extern __shared__ __nv_bfloat16 smb[];
    const int tid = threadIdx.x;
    const int lane = tid & 31, wid = tid >> 5;
    const int warp_m = wid >> 1, warp_n = wid & 1;   // 4x2 warp grid
    const int bm = blockIdx.y * 256, bn = blockIdx.x * 128;
    const uint32_t sb = smem_u32(smb);

    const int nstage = K / BK;   // 32

    auto load_stage = [&](int st, int buf) {
        const int kc0 = st * BK;
        uint32_t sbase = sb + (uint32_t)buf * STAGE_E * 2;
        #pragma unroll
        for (int i = 0; i < 4; i++) {      // A: 256 rows
            int e = tid + i * 256;
            int row = e >> 2, kc = (e & 3) * 8;
            uint32_t so = (uint32_t)(row * AST + kc) * 2;
            size_t ga = (size_t)(bm + row) * K + kc0 + kc;
            cp_async16(sbase + OFF_AHI*2 + so, Ahi + ga);
            cp_async16(sbase + OFF_ALO*2 + so, Alo + ga);
        }
        #pragma unroll
        for (int i = 0; i < 2; i++) {      // B: 128 rows
            int e = tid + i * 256;
            int row = e >> 2, kc = (e & 3) * 8;
            uint32_t so = (uint32_t)(row * AST + kc) * 2;
            size_t gb = (size_t)(bn + row) * K + kc0 + kc;
            cp_async16(sbase + OFF_BHI*2 + so, Bhi + gb);
            cp_async16(sbase + OFF_BLO*2 + so, Blo + gb);
        }
        cp_commit();
    };

    float d[4][8][4];
    #pragma unroll
    for (int mf = 0; mf < 4; mf++)
        #pragma unroll
        for (int nf = 0; nf < 8; nf++)
            #pragma unroll
            for (int r = 0; r < 4; r++) d[mf][nf][r] = 0.f;

    load_stage(0, 0);
    load_stage(1, 1);

    const int a_row = warp_m * 64 + (lane & 15);
    const int a_kh  = (lane >> 4) * 8;
    const int b_wn  = warp_n * 64;
    const int b_n   = (lane & 7) + ((lane >> 4) * 8);
    const int b_kh  = ((lane >> 3) & 1) * 8;

    for (int c = 0; c < nstage; c++) {
        if (c + 1 < nstage) cp_wait<1>(); else cp_wait<0>();
        __syncthreads();
        if (c + 2 < nstage) load_stage(c + 2, (c + 2) % NSTG);

        uint32_t tbase = sb + (uint32_t)((c % NSTG) * STAGE_E) * 2;
        #pragma unroll
        for (int ks = 0; ks < 2; ks++) {
            const int ko = ks * 16;
            uint32_t ah[4][4], al[4][4];
            #pragma unroll
            for (int mf = 0; mf < 4; mf++) {
                uint32_t off = (uint32_t)((a_row + mf * 16) * AST + ko + a_kh) * 2;
                ldsm4(ah[mf], tbase + OFF_AHI*2 + off);
                ldsm4(al[mf], tbase + OFF_ALO*2 + off);
            }
            #pragma unroll
            for (int g = 0; g < 4; g++) {      // 16-col B groups
                uint32_t bh[4], bl[4];
                uint32_t off = (uint32_t)((b_wn + g * 16 + b_n) * AST + ko + b_kh) * 2;
                ldsm4(bh, tbase + OFF_BHI*2 + off);
                ldsm4(bl, tbase + OFF_BLO*2 + off);
                // pass 1: hi*hi (8 independent accumulators)
                #pragma unroll
                for (int mf = 0; mf < 4; mf++) {
                    mma_bf16(d[mf][g*2+0], ah[mf], bh[0], bh[1]);
                    mma_bf16(d[mf][g*2+1], ah[mf], bh[2], bh[3]);
                }
                // pass 2: hi*lo
                #pragma unroll
                for (int mf = 0; mf < 4; mf++) {
                    mma_bf16(d[mf][g*2+0], ah[mf], bl[0], bl[1]);
                    mma_bf16(d[mf][g*2+1], ah[mf], bl[2], bl[3]);
                }
                // pass 3: lo*hi
                #pragma unroll
                for (int mf = 0; mf < 4; mf++) {
                    mma_bf16(d[mf][g*2+0], al[mf], bh[0], bh[1]);
                    mma_bf16(d[mf][g*2+1], al[mf], bh[2], bh[3]);
                }
            }
        }
    }

    // Epilogue (warp covers 64 rows x 64 cols)
    const int er = lane >> 2;
    const int ec = (lane & 3) * 2;
    #pragma unroll
    for (int mf = 0; mf < 4; mf++) {
        #pragma unroll
        for (int half = 0; half < 2; half++) {
            int gm = bm + warp_m * 64 + mf * 16 + er + half * 8;
            #pragma unroll
            for (int nf = 0; nf < 8; nf++) {
                int gn = bn + warp_n * 64 + nf * 8 + ec;
                float v0 = d[mf][nf][half * 2 + 0] + bias[gn];
                float v1 = d[mf][nf][half * 2 + 1] + bias[gn + 1];
                if (MODE == 0) {
                    float2 vv = {v0, v1};
                    *(float2*)(C + (size_t)gm * N + gn) = vv;
                } else {
                    int part = gn >> 10;
                    int col  = gn & 1023;
                    int h = col >> 6, dd = col & 63;   // dd even
                    int b = gm >> 11, s = gm & 2047;
                    size_t idx = (((size_t)(b * HH + h)) * SS + s) * HD + dd;
                    __nv_bfloat162 hh, ll;
                    hh.x = __float2bfloat16(v0);
                    hh.y = __float2bfloat16(v1);
                    ll.x = __float2bfloat16(v0 - __bfloat162float(hh.x));
                    ll.y = __float2bfloat16(v1 - __bfloat162float(hh.y));
                    if (part == 0) {
                        *(__nv_bfloat162*)(qhg + idx) = hh;
                        *(__nv_bfloat162*)(qlg + idx) = ll;
                    } else if (part == 1) {
                        float2 vv = {v0, v1};
                        *(float2*)(pk + idx) = vv;
                        *(__nv_bfloat162*)(khg + idx) = hh;
                        *(__nv_bfloat162*)(klg + idx) = ll;
                    } else {
                        float2 vv = {v0, v1};
                        *(float2*)(pv + idx) = vv;
                        size_t it = (((size_t)(b * HH + h)) * HD + dd) * SS + s;
                        vthg[it]      = hh.x;
                        vthg[it + SS] = hh.y;
                        vtlg[it]      = ll.x;
                        vtlg[it + SS] = ll.y;
                    }
                }
            }
        }
    }
}

// ---------------------------------------------------------------------------
// HMMA flash attention. BM=128 (8 warps x 16 rows), BN=64 keys/stage,
// 3-stage cp.async pipeline. Split MMAs issued in 3 passes.
// ---------------------------------------------------------------------------
#define ATLD 72                       // smem row stride (elems)
#define AT_OQH 0
#define AT_OQL (128*ATLD)             // 9216
#define AT_OST (2*128*ATLD)           // 18432
#define AT_KVT (64*ATLD)              // 4608 elems per sub-tile
#define AT_STAGE (4*AT_KVT)           // 18432 elems
#define AT_NSTG 3
#define AT_SMEM_B ((AT_OST + AT_NSTG*AT_STAGE)*2)   // 147456 bytes

__global__ __launch_bounds__(256, 1) void attn_mma(
    const __nv_bfloat16* __restrict__ qh, const __nv_bfloat16* __restrict__ ql,
    const __nv_bfloat16* __restrict__ kh, const __nv_bfloat16* __restrict__ kl,
    const __nv_bfloat16* __restrict__ vth, const __nv_bfloat16* __restrict__ vtl,
    __nv_bfloat16* __restrict__ Oh, __nv_bfloat16* __restrict__ Ol)
{
    extern __shared__ __nv_bfloat16 smb[];
    const uint32_t sb = smem_u32(smb);
    const int tid = threadIdx.x, lane = tid & 31, wid = tid >> 5;
    const int qt = 15 - blockIdx.x, bh = blockIdx.y;
    const int q0 = qt * 128;
    const int b = bh >> 4, h = bh & 15;

    // Q tiles (hi/lo), 128x64 (joins commit group 0)
    {
        const __nv_bfloat16* qhb = qh + ((size_t)bh * SS + q0) * HD;
        const __nv_bfloat16* qlb = ql + ((size_t)bh * SS + q0) * HD;
        #pragma unroll
        for (int i = 0; i < 4; i++) {
            int e = tid + i * 256;
            int row = e >> 3, c16 = e & 7;
            uint32_t so = (uint32_t)(row * ATLD + c16 * 8) * 2;
            cp_async16(sb + AT_OQH*2 + so, qhb + row * HD + c16 * 8);
            cp_async16(sb + AT_OQL*2 + so, qlb + row * HD + c16 * 8);
        }
    }

    const int ntile = 2 * (qt + 1);
    auto load_kv = [&](int kt, int buf) {
        const int k0 = kt * 64;
        uint32_t base = sb + (uint32_t)(AT_OST + buf * AT_STAGE) * 2;
        #pragma unroll
        for (int i = 0; i < 2; i++) {
            int e = tid + i * 256;
            int row = e >> 3, c16 = e & 7;
            uint32_t so = (uint32_t)(row * ATLD + c16 * 8) * 2;
            size_t gk = ((size_t)bh * SS + k0 + row) * HD + c16 * 8;
            size_t gv = ((size_t)bh * HD + row) * SS + k0 + c16 * 8;
            cp_async16(base + 0*AT_KVT*2 + so, kh + gk);
            cp_async16(base + 1*AT_KVT*2 + so, kl + gk);
            cp_async16(base + 2*AT_KVT*2 + so, vth + gv);
            cp_async16(base + 3*AT_KVT*2 + so, vtl + gv);
        }
        cp_commit();
    };
    load_kv(0, 0);   // group 0 also covers the Q chunks
    load_kv(1, 1);

    const int er = lane >> 2, ec = (lane & 3) * 2;
    const int a_row = wid * 16 + (lane & 15);
    const int a_kh = (lane >> 4) * 8;
    const int b_n = (lane & 7) + ((lane >> 4) * 8);
    const int b_kh = ((lane >> 3) & 1) * 8;

    float m0 = -1e30f, m1 = -1e30f, l0 = 0.f, l1 = 0.f;
    float o[8][4];
    #pragma unroll
    for (int nf = 0; nf < 8; nf++)
        #pragma unroll
        for (int r = 0; r < 4; r++) o[nf][r] = 0.f;

    for (int kt = 0; kt < ntile; kt++) {
        if (kt + 1 < ntile) cp_wait<1>(); else cp_wait<0>();
        __syncthreads();
        if (kt + 2 < ntile) load_kv(kt + 2, (kt + 2) % AT_NSTG);

        const uint32_t stg = sb + (uint32_t)(AT_OST + (kt % AT_NSTG) * AT_STAGE) * 2;
        const int k0 = kt * 64;

        // S = Q K^T (x3 split, 3 separated passes)
        float c[8][4];
        #pragma unroll
        for (int nf = 0; nf < 8; nf++)
            #pragma unroll
            for (int r = 0; r < 4; r++) c[nf][r] = 0.f;

        #pragma unroll
        for (int ks = 0; ks < 4; ks++) {
            uint32_t aoff = (uint32_t)(a_row * ATLD + ks * 16 + a_kh) * 2;
            uint32_t aH[4], aL[4];
            ldsm4(aH, sb + AT_OQH*2 + aoff);
            ldsm4(aL, sb + AT_OQL*2 + aoff);
            uint32_t bH[4][4], bL[4][4];
            #pragma unroll
            for (int q = 0; q < 4; q++) {
                uint32_t boff = (uint32_t)((q * 16 + b_n) * ATLD + ks * 16 + b_kh) * 2;
                ldsm4(bH[q], stg + 0*AT_KVT*2 + boff);
                ldsm4(bL[q], stg + 1*AT_KVT*2 + boff);
            }
            #pragma unroll
            for (int nf = 0; nf < 8; nf++) {
                int q = nf >> 1, p = (nf & 1) * 2;
                mma_bf16(c[nf], aH, bH[q][p], bH[q][p+1]);
            }
            #pragma unroll
            for (int nf = 0; nf < 8; nf++) {
                int q = nf >> 1, p = (nf & 1) * 2;
                mma_bf16(c[nf], aH, bL[q][p], bL[q][p+1]);
            }
            #pragma unroll
            for (int nf = 0; nf < 8; nf++) {
                int q = nf >> 1, p = (nf & 1) * 2;
                mma_bf16(c[nf], aL, bH[q][p], bH[q][p+1]);
            }
        }

        // scale + causal mask
        const int qi0 = q0 + wid * 16 + er;
        if (k0 + 63 > q0 + wid * 16) {
            #pragma unroll
            for (int nf = 0; nf < 8; nf++) {
                int jg = k0 + nf * 8 + ec;
                c[nf][0] = (jg     <= qi0    ) ? c[nf][0] * 0.125f : -1e10f;
                c[nf][1] = (jg + 1 <= qi0    ) ? c[nf][1] * 0.125f : -1e10f;
                c[nf][2] = (jg     <= qi0 + 8) ? c[nf][2] * 0.125f : -1e10f;
                c[nf][3] = (jg + 1 <= qi0 + 8) ? c[nf][3] * 0.125f : -1e10f;
            }
        } else {
            #pragma unroll
            for (int nf = 0; nf < 8; nf++)
                #pragma unroll
                for (int r = 0; r < 4; r++) c[nf][r] *= 0.125f;
        }

        // online softmax (rows er, er+8; quad-lane reduction)
        float rm0 = -1e30f, rm1 = -1e30f;
        #pragma unroll
        for (int nf = 0; nf < 8; nf++) {
            rm0 = fmaxf(rm0, fmaxf(c[nf][0], c[nf][1]));
            rm1 = fmaxf(rm1, fmaxf(c[nf][2], c[nf][3]));
        }
        #pragma unroll
        for (int off = 1; off < 4; off <<= 1) {
            rm0 = fmaxf(rm0, __shfl_xor_sync(0xffffffffu, rm0, off));
            rm1 = fmaxf(rm1, __shfl_xor_sync(0xffffffffu, rm1, off));
        }
        float mn0 = fmaxf(m0, rm0), mn1 = fmaxf(m1, rm1);
        float sc0 = __expf(m0 - mn0), sc1 = __expf(m1 - mn1);
        float rs0 = 0.f, rs1 = 0.f;
        #pragma unroll
        for (int nf = 0; nf < 8; nf++) {
            c[nf][0] = __expf(c[nf][0] - mn0);
            c[nf][1] = __expf(c[nf][1] - mn0);
            c[nf][2] = __expf(c[nf][2] - mn1);
            c[nf][3] = __expf(c[nf][3] - mn1);
            rs0 += c[nf][0] + c[nf][1];
            rs1 += c[nf][2] + c[nf][3];
        }
        #pragma unroll
        for (int off = 1; off < 4; off <<= 1) {
            rs0 += __shfl_xor_sync(0xffffffffu, rs0, off);
            rs1 += __shfl_xor_sync(0xffffffffu, rs1, off);
        }
        l0 = l0 * sc0 + rs0;  l1 = l1 * sc1 + rs1;
        m0 = mn0;  m1 = mn1;
        #pragma unroll
        for (int nf = 0; nf < 8; nf++) {
            o[nf][0] *= sc0; o[nf][1] *= sc0;
            o[nf][2] *= sc1; o[nf][3] *= sc1;
        }

        // O += P V  (x3 split; P frags re-packed; 3 separated passes)
        #pragma unroll
        for (int ks = 0; ks < 4; ks++) {
            uint32_t pH[4], pL[4];
            {
                float p00 = c[2*ks][0],   p01 = c[2*ks][1];
                float p10 = c[2*ks][2],   p11 = c[2*ks][3];
                float p20 = c[2*ks+1][0], p21 = c[2*ks+1][1];
                float p30 = c[2*ks+1][2], p31 = c[2*ks+1][3];
                __nv_bfloat162 h0 = __floats2bfloat162_rn(p00, p01);
                __nv_bfloat162 h1 = __floats2bfloat162_rn(p10, p11);
                __nv_bfloat162 h2 = __floats2bfloat162_rn(p20, p21);
                __nv_bfloat162 h3 = __floats2bfloat162_rn(p30, p31);
                pH[0] = *(uint32_t*)&h0; pH[1] = *(uint32_t*)&h1;
                pH[2] = *(uint32_t*)&h2; pH[3] = *(uint32_t*)&h3;
                __nv_bfloat162 l0v = __floats2bfloat162_rn(p00 - __bfloat162float(h0.x), p01 - __bfloat162float(h0.y));
                __nv_bfloat162 l1v = __floats2bfloat162_rn(p10 - __bfloat162float(h1.x), p11 - __bfloat162float(h1.y));
                __nv_bfloat162 l2v = __floats2bfloat162_rn(p20 - __bfloat162float(h2.x), p21 - __bfloat162float(h2.y));
                __nv_bfloat162 l3v = __floats2bfloat162_rn(p30 - __bfloat162float(h3.x), p31 - __bfloat162float(h3.y));
                pL[0] = *(uint32_t*)&l0v; pL[1] = *(uint32_t*)&l1v;
                pL[2] = *(uint32_t*)&l2v; pL[3] = *(uint32_t*)&l3v;
            }
            uint32_t vH[4][4], vL[4][4];
            #pragma unroll
            for (int qd = 0; qd < 4; qd++) {
                uint32_t boff = (uint32_t)((qd * 16 + b_n) * ATLD + ks * 16 + b_kh) * 2;
                ldsm4(vH[qd], stg + 2*AT_KVT*2 + boff);
                ldsm4(vL[qd], stg + 3*AT_KVT*2 + boff);
            }
            #pragma unroll
            for (int nf = 0; nf < 8; nf++) {
                int q = nf >> 1, p = (nf & 1) * 2;
                mma_bf16(o[nf], pH, vH[q][p], vH[q][p+1]);
            }
            #pragma unroll
            for (int nf = 0; nf < 8; nf++) {
                int q = nf >> 1, p = (nf & 1) * 2;
                mma_bf16(o[nf], pH, vL[q][p], vL[q][p+1]);
            }
            #pragma unroll
            for (int nf = 0; nf < 8; nf++) {
                int q = nf >> 1, p = (nf & 1) * 2;
                mma_bf16(o[nf], pL, vH[q][p], vH[q][p+1]);
            }
        }
    }

    // epilogue: write bf16 hi/lo merged (B,S,D)
    const float i0 = 1.f / l0, i1 = 1.f / l1;
    #pragma unroll
    for (int nf = 0; nf < 8; nf++) {
        int col = nf * 8 + ec;
        int row0 = q0 + wid * 16 + er;
        size_t off0 = ((size_t)(b * SS + row0)) * DD + h * HD + col;
        size_t off1 = off0 + (size_t)8 * DD;
        float a0 = o[nf][0] * i0, a1 = o[nf][1] * i0;
        float a2 = o[nf][2] * i1, a3 = o[nf][3] * i1;
        __nv_bfloat162 hh0, hh1, ll0, ll1;
        hh0.x = __float2bfloat16(a0); hh0.y = __float2bfloat16(a1);
        hh1.x = __float2bfloat16(a2); hh1.y = __float2bfloat16(a3);
        ll0.x = __float2bfloat16(a0 - __bfloat162float(hh0.x));
        ll0.y = __float2bfloat16(a1 - __bfloat162float(hh0.y));
        ll1.x = __float2bfloat16(a2 - __bfloat162float(hh1.x));
        ll1.y = __float2bfloat16(a3 - __bfloat162float(hh1.y));
        *(__nv_bfloat162*)(Oh + off0) = hh0;
        *(__nv_bfloat162*)(Ol + off0) = ll0;
        *(__nv_bfloat162*)(Oh + off1) = hh1;
        *(__nv_bfloat162*)(Ol + off1) = ll1;
    }
}

// ---------------------------------------------------------------------------
extern "C" void kernel_launch(void* const* d_in, const int* in_sizes, int n_in,
                              void* d_out, int out_size)
{
    const float* x        = (const float*)d_in[0];
    const float* c_attn_w = (const float*)d_in[1];
    const float* c_attn_b = (const float*)d_in[2];
    const float* c_proj_w = (const float*)d_in[3];
    const float* c_proj_b = (const float*)d_in[4];

    float* out   = (float*)d_out;
    float* a_out = out;
    float* pk    = out + A_ELEMS;
    float* pv    = pk + KV_ELEMS;

    __nv_bfloat16 *w1h, *w1l, *w2h, *w2l, *xh, *xl, *ah, *al;
    __nv_bfloat16 *qh, *ql, *kh, *kl, *vth, *vtl;
    cudaGetSymbolAddress((void**)&w1h, g_w1h);
    cudaGetSymbolAddress((void**)&w1l, g_w1l);
    cudaGetSymbolAddress((void**)&w2h, g_w2h);
    cudaGetSymbolAddress((void**)&w2l, g_w2l);
    cudaGetSymbolAddress((void**)&xh, g_xh);
    cudaGetSymbolAddress((void**)&xl, g_xl);
    cudaGetSymbolAddress((void**)&ah, g_ah);
    cudaGetSymbolAddress((void**)&al, g_al);
    cudaGetSymbolAddress((void**)&qh, g_qh);
    cudaGetSymbolAddress((void**)&ql, g_ql);
    cudaGetSymbolAddress((void**)&kh, g_kh);
    cudaGetSymbolAddress((void**)&kl, g_kl);
    cudaGetSymbolAddress((void**)&vth, g_vth);
    cudaGetSymbolAddress((void**)&vtl, g_vtl);

    cudaFuncSetAttribute(gemm_mma<0>, cudaFuncAttributeMaxDynamicSharedMemorySize, GEMM_SMEM);
    cudaFuncSetAttribute(gemm_mma<1>, cudaFuncAttributeMaxDynamicSharedMemorySize, GEMM_SMEM);
    cudaFuncSetAttribute(attn_mma, cudaFuncAttributeMaxDynamicSharedMemorySize, AT_SMEM_B);

    // 0) conversions
    conv_w<<<dim3(3072/32, 1024/32), 256>>>(c_attn_w, w1h, w1l, DD, 3*DD);
    conv_w<<<dim3(1024/32, 1024/32), 256>>>(c_proj_w, w2h, w2l, DD, DD);
    conv_split<<<A_ELEMS/1024, 256>>>(x, xh, xl);

    // 1) qkv = x @ c_attn_w + b -> present fp32 + q/k/vT bf16 hi/lo
    gemm_mma<1><<<dim3(3*DD/128, MTOT/256), 256, GEMM_SMEM>>>(
        xh, xl, w1h, w1l, c_attn_b, nullptr, pk, pv,
        qh, ql, kh, kl, vth, vtl, MTOT, 3*DD, DD);

    // 2) attention (HMMA) -> bf16 hi/lo
    attn_mma<<<dim3(SS/128, BB*HH), 256, AT_SMEM_B>>>(
        qh, ql, kh, kl, vth, vtl, ah, al);

    // 3) proj (HMMA)
    gemm_mma<0><<<dim3(DD/128, MTOT/256), 256, GEMM_SMEM>>>(
        ah, al, w2h, w2l, c_proj_b, a_out, nullptr, nullptr,
        nullptr, nullptr, nullptr, nullptr, nullptr, nullptr, MTOT, DD, DD);
}